// round 16
// baseline (speedup 1.0000x reference)
#include <cuda_runtime.h>
#include <cuda_bf16.h>

#define HH 256
#define WW 256
#define NIMG (64*21)
#define BAND 64              // output rows per CTA
#define NBAND (HH / BAND)    // 4
#define NTHR 64              // one thread per 4 columns, full row per CTA

// Packed f32x2 FMA (Blackwell FFMA2) — ptxas never emits this from C++.
__device__ __forceinline__ float2 ffma2(float2 a, float2 b, float2 c) {
    float2 d;
    asm("fma.rn.f32x2 %0, %1, %2, %3;"
        : "=l"(reinterpret_cast<unsigned long long&>(d))
        : "l"(reinterpret_cast<unsigned long long&>(a)),
          "l"(reinterpret_cast<unsigned long long&>(b)),
          "l"(reinterpret_cast<unsigned long long&>(c)));
    return d;
}

// Gaussian symmetric: g[j] == g[8-j] bit-exactly (row sums of symmetric kernel).
#define GG(j) gg[((j) < 5) ? (j) : (8 - (j))]
#define GS(j) (GG(j).x)

__global__ __launch_bounds__(NTHR, 12)
void heatmap_stream_kernel(const int* __restrict__ coords,
                           const float* __restrict__ noise,
                           const float* __restrict__ k2d,
                           float* __restrict__ out)
{
    __shared__ float gsm[9];   // 1D taps, runtime-indexable for the peak epilogue

    const int tid = threadIdx.x;
    const int band = blockIdx.x;
    const int img = blockIdx.y;
    const int y0 = band * BAND;
    const int x = tid * 4;

    if (tid < 9) {
        float s = 0.f;
        #pragma unroll
        for (int j = 0; j < 9; j++) s += k2d[tid * 9 + j];
        gsm[tid] = s;
    }
    __syncthreads();   // the only barrier in the kernel

    float2 gg[5];
    #pragma unroll
    for (int i = 0; i < 5; i++) gg[i] = make_float2(gsm[i], gsm[i]);

    const float* __restrict__ np = noise + (size_t)img * (HH * WW);
    const int cx = coords[2 * img];
    const int cy = coords[2 * img + 1];
    // Peak correction by linearity: out = relu(0.01*conv(noise) + delta*g[dy]*g[dx])
    const float delta = 1.0f / __ldg(&k2d[40]) - 0.01f * __ldg(&np[cy * WW + cx]);

    // 9-slot ring: slot s holds the pending output o with (o - y0) % 9 == s.
    float2 A0[9], A1[9];
    #pragma unroll
    for (int s = 0; s < 9; s++) {
        A0[s] = make_float2(0.f, 0.f);
        A1[s] = make_float2(0.f, 0.f);
    }

    float* orow = out + (size_t)img * (HH * WW) + (size_t)y0 * WW + x;

    // Per-input-row body. FIRST (compile-time): warmup block, where slot s only
    // joins once its output window has started (s <= u). All indices fold.
#define PROC_ROW(OB, U, FIRST)                                                \
    {                                                                         \
        const int ir = (OB) * 9 + (U);                                        \
        const int gy = y0 - 4 + ir;                                           \
        if (gy >= 0 && gy < HH) {            /* warp-uniform */               \
            const float* rp = np + gy * WW + x;                               \
            float4 C = *(const float4*)(rp);                                  \
            float4 L = (x >= 4) ? *(const float4*)(rp - 4)                    \
                                : make_float4(0.f, 0.f, 0.f, 0.f);            \
            float4 R = (x < WW - 4) ? *(const float4*)(rp + 4)                \
                                    : make_float4(0.f, 0.f, 0.f, 0.f);        \
            float v[12] = {L.x, L.y, L.z, L.w, C.x, C.y, C.z, C.w,            \
                           R.x, R.y, R.z, R.w};                               \
            float h0 = 0.f, h1 = 0.f, h2 = 0.f, h3 = 0.f;                     \
            _Pragma("unroll")                                                 \
            for (int j = 0; j < 9; j++) {                                     \
                const float gj = GS(j);                                       \
                h0 = fmaf(gj, v[j],     h0);                                  \
                h1 = fmaf(gj, v[j + 1], h1);                                  \
                h2 = fmaf(gj, v[j + 2], h2);                                  \
                h3 = fmaf(gj, v[j + 3], h3);                                  \
            }                                                                 \
            const float2 hp0 = make_float2(h0, h1);                           \
            const float2 hp1 = make_float2(h2, h3);                           \
            _Pragma("unroll")                                                 \
            for (int s = 0; s < 9; s++) {                                     \
                if (!(FIRST) || s <= (U)) {                                   \
                    const int i = ((U) - s + 9) % 9;                          \
                    A0[s] = ffma2(GG(i), hp0, A0[s]);                         \
                    A1[s] = ffma2(GG(i), hp1, A1[s]);                         \
                }                                                             \
            }                                                                 \
        }                                                                     \
        if (ir >= 8) {                        /* output o = y0+ir-8 done */   \
            const int sc = ((U) + 1) % 9;                                     \
            const int o = y0 + ir - 8;                                        \
            float val0 = 0.01f * A0[sc].x;                                    \
            float val1 = 0.01f * A0[sc].y;                                    \
            float val2 = 0.01f * A1[sc].x;                                    \
            float val3 = 0.01f * A1[sc].y;                                    \
            const int dy = o - cy + 4;                                        \
            if ((unsigned)dy <= 8u) {         /* rare: peak row footprint */  \
                const float w = delta * gsm[dy];                              \
                _Pragma("unroll")                                             \
                for (int cc = 0; cc < 4; cc++) {                              \
                    const int dx = x + cc - cx + 4;                           \
                    if ((unsigned)dx <= 8u) {                                 \
                        const float add = w * gsm[dx];                        \
                        if (cc == 0) val0 += add;                             \
                        else if (cc == 1) val1 += add;                        \
                        else if (cc == 2) val2 += add;                        \
                        else val3 += add;                                     \
                    }                                                         \
                }                                                             \
            }                                                                 \
            float4 ov = make_float4(fmaxf(val0, 0.f), fmaxf(val1, 0.f),       \
                                    fmaxf(val2, 0.f), fmaxf(val3, 0.f));      \
            *(float4*)orow = ov;                                              \
            orow += WW;                                                       \
            A0[sc] = make_float2(0.f, 0.f);                                   \
            A1[sc] = make_float2(0.f, 0.f);                                   \
        }                                                                     \
    }

    // Warmup block (ir = 0..8): guarded slot joins.
    #pragma unroll
    for (int u = 0; u < 9; u++) PROC_ROW(0, u, true)

    // Steady state (ir = 9..71): all slots active.
    for (int ob = 1; ob < 8; ob++) {
        #pragma unroll
        for (int u = 0; u < 9; u++) PROC_ROW(ob, u, false)
    }
#undef PROC_ROW
}

extern "C" void kernel_launch(void* const* d_in, const int* in_sizes, int n_in,
                              void* d_out, int out_size)
{
    const int* coords = nullptr;
    const float* noise = nullptr;
    const float* k2d = nullptr;
    for (int i = 0; i < n_in; i++) {
        if (in_sizes[i] == 81)            k2d    = (const float*)d_in[i];
        else if (in_sizes[i] == 64*21*2)  coords = (const int*)d_in[i];
        else                              noise  = (const float*)d_in[i];
    }

    dim3 grid(NBAND, NIMG);
    heatmap_stream_kernel<<<grid, NTHR>>>(coords, noise, k2d, (float*)d_out);
}

// round 17
// speedup vs baseline: 1.0852x; 1.0852x over previous
#include <cuda_runtime.h>
#include <cuda_bf16.h>

#define HH 256
#define WW 256
#define NIMG (64*21)
#define BAND 64              // output rows per CTA
#define NBAND (HH / BAND)    // 4
#define NTHR 64              // one thread per 4 columns, full row per CTA

// Packed f32x2 FMA (Blackwell FFMA2) — ptxas never emits this from C++.
__device__ __forceinline__ float2 ffma2(float2 a, float2 b, float2 c) {
    float2 d;
    asm("fma.rn.f32x2 %0, %1, %2, %3;"
        : "=l"(reinterpret_cast<unsigned long long&>(d))
        : "l"(reinterpret_cast<unsigned long long&>(a)),
          "l"(reinterpret_cast<unsigned long long&>(b)),
          "l"(reinterpret_cast<unsigned long long&>(c)));
    return d;
}

// Gaussian symmetric: g[j] == g[8-j] bit-exactly (row sums of symmetric kernel).
#define GG(j) gg[((j) < 5) ? (j) : (8 - (j))]
#define GS(j) (GG(j).x)

__global__ __launch_bounds__(NTHR, 11)
void heatmap_stream_kernel(const int* __restrict__ coords,
                           const float* __restrict__ noise,
                           const float* __restrict__ k2d,
                           float* __restrict__ out)
{
    __shared__ float gsm[9];   // 1D taps, runtime-indexable for the peak epilogue

    const int tid = threadIdx.x;
    const int band = blockIdx.x;
    const int img = blockIdx.y;
    const int y0 = band * BAND;
    const int x = tid * 4;

    if (tid < 9) {
        float s = 0.f;
        #pragma unroll
        for (int j = 0; j < 9; j++) s += k2d[tid * 9 + j];
        gsm[tid] = s;
    }
    __syncthreads();   // the only barrier in the kernel

    float2 gg[5];
    #pragma unroll
    for (int i = 0; i < 5; i++) gg[i] = make_float2(gsm[i], gsm[i]);

    const float* __restrict__ np = noise + (size_t)img * (HH * WW);
    const int cx = coords[2 * img];
    const int cy = coords[2 * img + 1];
    // Peak correction by linearity: out = relu(0.01*conv(noise) + delta*g[dy]*g[dx])
    const float delta = 1.0f / __ldg(&k2d[40]) - 0.01f * __ldg(&np[cy * WW + cx]);

    // 9-slot ring: slot s holds the pending output o with (o - y0) % 9 == s.
    float2 A0[9], A1[9];
    #pragma unroll
    for (int s = 0; s < 9; s++) {
        A0[s] = make_float2(0.f, 0.f);
        A1[s] = make_float2(0.f, 0.f);
    }

    float* orow = out + (size_t)img * (HH * WW) + (size_t)y0 * WW + x;

    const bool okL = (x >= 4);
    const bool okR = (x < WW - 4);

    // Row loader (zero-fill out of range). Warp-uniform gy branch.
#define LOADROW(GY, L_, C_, R_)                                               \
    {                                                                         \
        if ((GY) >= 0 && (GY) < HH) {                                         \
            const float* rp = np + (GY) * WW + x;                             \
            C_ = *(const float4*)(rp);                                        \
            L_ = okL ? *(const float4*)(rp - 4)                               \
                     : make_float4(0.f, 0.f, 0.f, 0.f);                       \
            R_ = okR ? *(const float4*)(rp + 4)                               \
                     : make_float4(0.f, 0.f, 0.f, 0.f);                       \
        } else {                                                              \
            L_ = make_float4(0.f, 0.f, 0.f, 0.f);                             \
            C_ = make_float4(0.f, 0.f, 0.f, 0.f);                             \
            R_ = make_float4(0.f, 0.f, 0.f, 0.f);                             \
        }                                                                     \
    }

    // Prefetch pipeline registers (consumed one row-step later).
    float4 pL, pC, pR;
    LOADROW(y0 - 4, pL, pC, pR);

    // Per-input-row body. FIRST (compile-time): warmup block, where slot s only
    // joins once its output's window has started (s <= u). Branch-free compute:
    // OOB rows are zero-filled and contribute nothing.
#define PROC_ROW(OB, U, FIRST)                                                \
    {                                                                         \
        const int ir = (OB) * 9 + (U);                                        \
        const float4 L = pL, C = pC, R = pR;                                  \
        if (ir < BAND + 7) {               /* prefetch row ir+1 */            \
            const int gyn = y0 - 3 + ir;                                      \
            LOADROW(gyn, pL, pC, pR);                                         \
        }                                                                     \
        const float v[12] = {L.x, L.y, L.z, L.w, C.x, C.y, C.z, C.w,          \
                             R.x, R.y, R.z, R.w};                             \
        float h0 = 0.f, h1 = 0.f, h2 = 0.f, h3 = 0.f;                         \
        _Pragma("unroll")                                                     \
        for (int j = 0; j < 9; j++) {                                         \
            const float gj = GS(j);                                           \
            h0 = fmaf(gj, v[j],     h0);                                      \
            h1 = fmaf(gj, v[j + 1], h1);                                      \
            h2 = fmaf(gj, v[j + 2], h2);                                      \
            h3 = fmaf(gj, v[j + 3], h3);                                      \
        }                                                                     \
        const float2 hp0 = make_float2(h0, h1);                               \
        const float2 hp1 = make_float2(h2, h3);                               \
        _Pragma("unroll")                                                     \
        for (int s = 0; s < 9; s++) {                                         \
            if (!(FIRST) || s <= (U)) {                                       \
                const int i = ((U) - s + 9) % 9;                              \
                A0[s] = ffma2(GG(i), hp0, A0[s]);                             \
                A1[s] = ffma2(GG(i), hp1, A1[s]);                             \
            }                                                                 \
        }                                                                     \
        if (ir >= 8) {                     /* output o = y0+ir-8 finished */  \
            const int sc = ((U) + 1) % 9;                                     \
            const int o = y0 + ir - 8;                                        \
            float val0 = 0.01f * A0[sc].x;                                    \
            float val1 = 0.01f * A0[sc].y;                                    \
            float val2 = 0.01f * A1[sc].x;                                    \
            float val3 = 0.01f * A1[sc].y;                                    \
            const int dy = o - cy + 4;                                        \
            if ((unsigned)dy <= 8u) {      /* rare: peak row footprint */     \
                const float w = delta * gsm[dy];                              \
                _Pragma("unroll")                                             \
                for (int cc = 0; cc < 4; cc++) {                              \
                    const int dx = x + cc - cx + 4;                           \
                    if ((unsigned)dx <= 8u) {                                 \
                        const float add = w * gsm[dx];                        \
                        if (cc == 0) val0 += add;                             \
                        else if (cc == 1) val1 += add;                        \
                        else if (cc == 2) val2 += add;                        \
                        else val3 += add;                                     \
                    }                                                         \
                }                                                             \
            }                                                                 \
            float4 ov = make_float4(fmaxf(val0, 0.f), fmaxf(val1, 0.f),       \
                                    fmaxf(val2, 0.f), fmaxf(val3, 0.f));      \
            *(float4*)orow = ov;                                              \
            orow += WW;                                                       \
            A0[sc] = make_float2(0.f, 0.f);                                   \
            A1[sc] = make_float2(0.f, 0.f);                                   \
        }                                                                     \
    }

    // Warmup block (ir = 0..8): guarded slot joins.
    #pragma unroll
    for (int u = 0; u < 9; u++) PROC_ROW(0, u, true)

    // Steady state (ir = 9..71): all slots active.
    for (int ob = 1; ob < 8; ob++) {
        #pragma unroll
        for (int u = 0; u < 9; u++) PROC_ROW(ob, u, false)
    }
#undef PROC_ROW
#undef LOADROW
}

extern "C" void kernel_launch(void* const* d_in, const int* in_sizes, int n_in,
                              void* d_out, int out_size)
{
    const int* coords = nullptr;
    const float* noise = nullptr;
    const float* k2d = nullptr;
    for (int i = 0; i < n_in; i++) {
        if (in_sizes[i] == 81)            k2d    = (const float*)d_in[i];
        else if (in_sizes[i] == 64*21*2)  coords = (const int*)d_in[i];
        else                              noise  = (const float*)d_in[i];
    }

    dim3 grid(NBAND, NIMG);
    heatmap_stream_kernel<<<grid, NTHR>>>(coords, noise, k2d, (float*)d_out);
}